// round 1
// baseline (speedup 1.0000x reference)
#include <cuda_runtime.h>
#include <cuda_bf16.h>

// Problem constants
#define QN 256   // states
#define SN 128   // symbols
#define BN 1024  // batch
#define TN 128   // timesteps
#define MTILE 8  // batch elements per work item

// Device scratch (allocation-free rule: static __device__ globals)
__device__ float g_P[SN * QN * QN];          // exp(A), layout [s][q][q'] : 32 MB (L2-resident)
__device__ float g_alpha[2][BN * QN];        // ping-pong alpha buffers (log space)
__device__ int   g_order[TN * BN];           // per-t batch indices sorted by symbol
__device__ int4  g_items[TN * 256];          // per-t work items: (symbol, start, cnt, pad)
__device__ int   g_nitems[TN];

// ---------------------------------------------------------------------------
// P[s][q][q'] = exp(A[q][s][q'])
__global__ void exp_kernel(const float* __restrict__ A) {
    int i = blockIdx.x * 256 + threadIdx.x;       // 0 .. 128*256*256-1
    int j = i & 255;
    int q = (i >> 8) & 255;
    int s = i >> 16;
    g_P[(s << 16) + (q << 8) + j] = __expf(A[(q << 15) + (s << 8) + j]);
}

// ---------------------------------------------------------------------------
// alpha0[b][q] = log_init[q]
__global__ void init_kernel(const float* __restrict__ init) {
    int b = blockIdx.x;
    int q = threadIdx.x;
    float iv = init[q];
    float v = (iv > 0.0f) ? __logf(fmaxf(iv, 1e-30f)) : -1e30f;
    g_alpha[0][b * QN + q] = v;
}

// ---------------------------------------------------------------------------
// Per-timestep bucketing: one CTA per t. Sorts batch indices by symbol and
// builds work items of <= MTILE elements. Atomic scatter order within a
// segment is nondeterministic but per-element results are order-independent.
__global__ void bucket_kernel(const int* __restrict__ xs) {
    int t = blockIdx.x;
    int tid = threadIdx.x;
    __shared__ int cnt[SN];
    __shared__ int seg[SN];
    __shared__ int off[SN];
    if (tid < SN) cnt[tid] = 0;
    __syncthreads();
    for (int b = tid; b < BN; b += 256)
        atomicAdd(&cnt[xs[b * TN + t]], 1);
    __syncthreads();
    if (tid == 0) {
        int acc = 0;
        for (int s = 0; s < SN; s++) { seg[s] = acc; off[s] = acc; acc += cnt[s]; }
    }
    __syncthreads();
    for (int b = tid; b < BN; b += 256) {
        int s = xs[b * TN + t];
        int pos = atomicAdd(&off[s], 1);
        g_order[t * BN + pos] = b;
    }
    __syncthreads();
    if (tid == 0) {
        int ni = 0;
        for (int s = 0; s < SN; s++) {
            int c = cnt[s], st = seg[s];
            for (int o = 0; o < c; o += MTILE) {
                int m = c - o; if (m > MTILE) m = MTILE;
                g_items[t * 256 + ni] = make_int4(s, st + o, m, 0);
                ni++;
            }
        }
        g_nitems[t] = ni;
    }
}

// ---------------------------------------------------------------------------
// One FSA step: for each work item (symbol s, up to 8 batch elems),
//   alpha_new[b][q'] = log( sum_q exp(alpha[b][q]-m_b) * P[s][q][q'] ) + m_b
// Thread j owns column q'=j. Matrix read once from L2 per item, reused x8.
__global__ void __launch_bounds__(256) step_kernel(int t) {
    const float* __restrict__ alpha_in  = g_alpha[t & 1];
    float*       __restrict__ alpha_out = g_alpha[(t & 1) ^ 1];
    if (blockIdx.x >= g_nitems[t]) return;
    int4 it = g_items[t * 256 + blockIdx.x];
    const int s = it.x, start = it.y, cnt = it.z;

    __shared__ float s_al[MTILE][QN];   // exp(alpha - m), zero-padded
    __shared__ float s_m[MTILE];
    __shared__ int   s_b[MTILE];

    const int tid = threadIdx.x;
    const int w = tid >> 5, lane = tid & 31;

    // 8 warps: warp w prepares batch element m=w
    if (w < cnt) {
        int b = g_order[t * BN + start + w];
        if (lane == 0) s_b[w] = b;
        const float* ar = alpha_in + b * QN;
        float v[8];
        float mx = -3.4e38f;
        #pragma unroll
        for (int i = 0; i < 8; i++) { v[i] = ar[lane + 32 * i]; mx = fmaxf(mx, v[i]); }
        #pragma unroll
        for (int o = 16; o > 0; o >>= 1) mx = fmaxf(mx, __shfl_xor_sync(0xFFFFFFFFu, mx, o));
        if (lane == 0) s_m[w] = mx;
        #pragma unroll
        for (int i = 0; i < 8; i++) s_al[w][lane + 32 * i] = __expf(fmaxf(v[i] - mx, -87.0f));
    } else {
        #pragma unroll
        for (int i = 0; i < 8; i++) s_al[w][lane + 32 * i] = 0.0f;
    }
    __syncthreads();

    float acc[MTILE];
    #pragma unroll
    for (int m = 0; m < MTILE; m++) acc[m] = 0.0f;

    const float* __restrict__ Pp = g_P + (s << 16) + tid;  // P[s][0][tid]
    #pragma unroll 4
    for (int q = 0; q < QN; q++) {
        float p = __ldg(Pp + (q << 8));      // coalesced 128B/warp per load
        #pragma unroll
        for (int m = 0; m < MTILE; m++)
            acc[m] = fmaf(p, s_al[m][q], acc[m]);  // s_al broadcast reads
    }

    for (int m = 0; m < cnt; m++)
        alpha_out[s_b[m] * QN + tid] = __logf(acc[m]) + s_m[m];
}

// ---------------------------------------------------------------------------
// out[b] = logsumexp_q(alphaT[b][q] + final[q]); warp per batch element.
__global__ void final_kernel(const float* __restrict__ finalw, float* __restrict__ out) {
    int b = blockIdx.x * 8 + (threadIdx.x >> 5);
    int lane = threadIdx.x & 31;
    const float* ar = g_alpha[0] + b * QN;   // T=128 even -> final alpha in buffer 0
    float v[8];
    float mx = -3.4e38f;
    #pragma unroll
    for (int i = 0; i < 8; i++) {
        v[i] = ar[lane + 32 * i] + finalw[lane + 32 * i];
        mx = fmaxf(mx, v[i]);
    }
    #pragma unroll
    for (int o = 16; o > 0; o >>= 1) mx = fmaxf(mx, __shfl_xor_sync(0xFFFFFFFFu, mx, o));
    float sum = 0.0f;
    #pragma unroll
    for (int i = 0; i < 8; i++) sum += __expf(v[i] - mx);
    #pragma unroll
    for (int o = 16; o > 0; o >>= 1) sum += __shfl_xor_sync(0xFFFFFFFFu, sum, o);
    if (lane == 0) out[b] = __logf(sum) + mx;
}

// ---------------------------------------------------------------------------
extern "C" void kernel_launch(void* const* d_in, const int* in_sizes, int n_in,
                              void* d_out, int out_size) {
    const float* A      = (const float*)d_in[0];  // [Q,S,Q] fp32
    const float* init   = (const float*)d_in[1];  // [Q]
    const float* finalw = (const float*)d_in[2];  // [Q]
    const int*   xs     = (const int*)d_in[3];    // [B,T] int32
    float* out = (float*)d_out;                   // [B]

    exp_kernel<<<(SN * QN * QN) / 256, 256>>>(A);
    init_kernel<<<BN, QN>>>(init);
    bucket_kernel<<<TN, 256>>>(xs);
    for (int t = 0; t < TN; t++)
        step_kernel<<<256, 256>>>(t);
    final_kernel<<<BN / 8, 256>>>(finalw, out);
}

// round 2
// speedup vs baseline: 1.3310x; 1.3310x over previous
#include <cuda_runtime.h>
#include <cuda_bf16.h>

// Problem constants
#define QN 256   // states
#define SN 128   // symbols
#define BN 1024  // batch
#define TN 128   // timesteps
#define MTILE 8  // batch elements per work item

// Device scratch (allocation-free rule: static __device__ globals)
__device__ float g_P[SN * QN * QN];          // exp(A), layout [s][q][q'] : 32 MB (L2-resident)
__device__ float g_alpha[2][BN * QN];        // ping-pong alpha buffers (log space)
__device__ int   g_order[TN * BN];           // per-t batch indices sorted by symbol
__device__ int4  g_items[TN * 256];          // per-t work items: (symbol, start, cnt, pad)
__device__ int   g_nitems[TN];

// Packed dual-FMA (Blackwell f32x2)
__device__ __forceinline__ void fma2(unsigned long long& d,
                                     unsigned long long a,
                                     unsigned long long b) {
    asm("fma.rn.f32x2 %0, %1, %2, %0;" : "+l"(d) : "l"(a), "l"(b));
}
__device__ __forceinline__ unsigned long long pack2(float x) {
    unsigned long long r;
    unsigned u = __float_as_uint(x);
    asm("mov.b64 %0, {%1, %1};" : "=l"(r) : "r"(u));
    return r;
}

// ---------------------------------------------------------------------------
// P[s][q][q'] = exp(A[q][s][q'])
__global__ void exp_kernel(const float* __restrict__ A) {
    int i = blockIdx.x * 256 + threadIdx.x;       // 0 .. 128*256*256-1
    int j = i & 255;
    int q = (i >> 8) & 255;
    int s = i >> 16;
    g_P[(s << 16) + (q << 8) + j] = __expf(A[(q << 15) + (s << 8) + j]);
}

// ---------------------------------------------------------------------------
// alpha0[b][q] = log_init[q]
__global__ void init_kernel(const float* __restrict__ init) {
    int b = blockIdx.x;
    int q = threadIdx.x;
    float iv = init[q];
    float v = (iv > 0.0f) ? __logf(fmaxf(iv, 1e-30f)) : -1e30f;
    g_alpha[0][b * QN + q] = v;
}

// ---------------------------------------------------------------------------
// Per-timestep bucketing: one CTA per t. Sorts batch indices by symbol and
// builds work items of <= MTILE elements. Atomic scatter order within a
// segment is nondeterministic but per-element results are order-independent.
__global__ void bucket_kernel(const int* __restrict__ xs) {
    int t = blockIdx.x;
    int tid = threadIdx.x;
    __shared__ int cnt[SN];
    __shared__ int seg[SN];
    __shared__ int off[SN];
    if (tid < SN) cnt[tid] = 0;
    __syncthreads();
    for (int b = tid; b < BN; b += 256)
        atomicAdd(&cnt[xs[b * TN + t]], 1);
    __syncthreads();
    if (tid == 0) {
        int acc = 0;
        for (int s = 0; s < SN; s++) { seg[s] = acc; off[s] = acc; acc += cnt[s]; }
    }
    __syncthreads();
    for (int b = tid; b < BN; b += 256) {
        int s = xs[b * TN + t];
        int pos = atomicAdd(&off[s], 1);
        g_order[t * BN + pos] = b;
    }
    __syncthreads();
    if (tid == 0) {
        int ni = 0;
        for (int s = 0; s < SN; s++) {
            int c = cnt[s], st = seg[s];
            for (int o = 0; o < c; o += MTILE) {
                int m = c - o; if (m > MTILE) m = MTILE;
                g_items[t * 256 + ni] = make_int4(s, st + o, m, 0);
                ni++;
            }
        }
        g_nitems[t] = ni;
    }
}

// ---------------------------------------------------------------------------
// One FSA step: for each work item (symbol s, up to 8 batch elems),
//   alpha_new[b][q'] = log( sum_q exp(alpha[b][q]-m_b) * P[s][q][q'] ) + m_b
// Thread j owns column q'=j. s_al is [q][m] so each q needs just two
// broadcast LDS.128; accumulation uses packed fma.rn.f32x2 over m-pairs.
__global__ void __launch_bounds__(256) step_kernel(int t) {
    const float* __restrict__ alpha_in  = g_alpha[t & 1];
    float*       __restrict__ alpha_out = g_alpha[(t & 1) ^ 1];
    if (blockIdx.x >= g_nitems[t]) return;
    int4 it = g_items[t * 256 + blockIdx.x];
    const int s = it.x, start = it.y, cnt = it.z;

    __shared__ __align__(16) float s_al[QN][MTILE];  // [q][m] exp(alpha-m), zero-padded
    __shared__ float s_m[MTILE];
    __shared__ int   s_b[MTILE];

    const int tid = threadIdx.x;
    const int w = tid >> 5, lane = tid & 31;

    // 8 warps: warp w prepares batch element m=w (writes transposed)
    if (w < cnt) {
        int b = g_order[t * BN + start + w];
        if (lane == 0) s_b[w] = b;
        const float* ar = alpha_in + b * QN;
        float v[8];
        float mx = -3.4e38f;
        #pragma unroll
        for (int i = 0; i < 8; i++) { v[i] = ar[lane + 32 * i]; mx = fmaxf(mx, v[i]); }
        #pragma unroll
        for (int o = 16; o > 0; o >>= 1) mx = fmaxf(mx, __shfl_xor_sync(0xFFFFFFFFu, mx, o));
        if (lane == 0) s_m[w] = mx;
        #pragma unroll
        for (int i = 0; i < 8; i++)
            s_al[lane + 32 * i][w] = __expf(fmaxf(v[i] - mx, -87.0f));
    } else {
        #pragma unroll
        for (int i = 0; i < 8; i++) s_al[lane + 32 * i][w] = 0.0f;
    }
    __syncthreads();

    unsigned long long acc[4] = {0ull, 0ull, 0ull, 0ull};  // m-pairs (0,1)(2,3)(4,5)(6,7)

    const float* __restrict__ Pp = g_P + (s << 16) + tid;  // P[s][0][tid]
    #pragma unroll
    for (int q0 = 0; q0 < QN; q0 += 8) {
        float p[8];
        #pragma unroll
        for (int i = 0; i < 8; i++)
            p[i] = __ldg(Pp + ((q0 + i) << 8));   // MLP=8, L2-resident, coalesced
        #pragma unroll
        for (int i = 0; i < 8; i++) {
            unsigned long long pp = pack2(p[i]);
            const ulonglong2* row = (const ulonglong2*)&s_al[q0 + i][0];
            ulonglong2 a0 = row[0];   // LDS.128 broadcast: m0..m3
            ulonglong2 a1 = row[1];   // LDS.128 broadcast: m4..m7
            fma2(acc[0], pp, a0.x);
            fma2(acc[1], pp, a0.y);
            fma2(acc[2], pp, a1.x);
            fma2(acc[3], pp, a1.y);
        }
    }

    #pragma unroll
    for (int j = 0; j < 4; j++) {
        int m0 = 2 * j, m1 = 2 * j + 1;
        float lo = __uint_as_float((unsigned)(acc[j] & 0xFFFFFFFFull));
        float hi = __uint_as_float((unsigned)(acc[j] >> 32));
        if (m0 < cnt) alpha_out[s_b[m0] * QN + tid] = __logf(lo) + s_m[m0];
        if (m1 < cnt) alpha_out[s_b[m1] * QN + tid] = __logf(hi) + s_m[m1];
    }
}

// ---------------------------------------------------------------------------
// out[b] = logsumexp_q(alphaT[b][q] + final[q]); warp per batch element.
__global__ void final_kernel(const float* __restrict__ finalw, float* __restrict__ out) {
    int b = blockIdx.x * 8 + (threadIdx.x >> 5);
    int lane = threadIdx.x & 31;
    const float* ar = g_alpha[0] + b * QN;   // T=128 even -> final alpha in buffer 0
    float v[8];
    float mx = -3.4e38f;
    #pragma unroll
    for (int i = 0; i < 8; i++) {
        v[i] = ar[lane + 32 * i] + finalw[lane + 32 * i];
        mx = fmaxf(mx, v[i]);
    }
    #pragma unroll
    for (int o = 16; o > 0; o >>= 1) mx = fmaxf(mx, __shfl_xor_sync(0xFFFFFFFFu, mx, o));
    float sum = 0.0f;
    #pragma unroll
    for (int i = 0; i < 8; i++) sum += __expf(v[i] - mx);
    #pragma unroll
    for (int o = 16; o > 0; o >>= 1) sum += __shfl_xor_sync(0xFFFFFFFFu, sum, o);
    if (lane == 0) out[b] = __logf(sum) + mx;
}

// ---------------------------------------------------------------------------
extern "C" void kernel_launch(void* const* d_in, const int* in_sizes, int n_in,
                              void* d_out, int out_size) {
    const float* A      = (const float*)d_in[0];  // [Q,S,Q] fp32
    const float* init   = (const float*)d_in[1];  // [Q]
    const float* finalw = (const float*)d_in[2];  // [Q]
    const int*   xs     = (const int*)d_in[3];    // [B,T] int32
    float* out = (float*)d_out;                   // [B]

    exp_kernel<<<(SN * QN * QN) / 256, 256>>>(A);
    init_kernel<<<BN, QN>>>(init);
    bucket_kernel<<<TN, 256>>>(xs);
    for (int t = 0; t < TN; t++)
        step_kernel<<<256, 256>>>(t);
    final_kernel<<<BN / 8, 256>>>(finalw, out);
}

// round 3
// speedup vs baseline: 1.5842x; 1.1902x over previous
#include <cuda_runtime.h>
#include <cuda_bf16.h>

// Problem constants
#define QN 256   // states
#define SN 128   // symbols
#define BN 1024  // batch
#define TN 128   // timesteps
#define MTILE 8  // batch elements per work item
#define KSPLIT 4 // q-chunks per item
#define QCH 64   // QN / KSPLIT

// Device scratch (allocation-free rule: static __device__ globals)
__device__ float g_P[SN * QN * QN];            // exp(A), [s][q][q'] : 32 MB (L2-resident)
__device__ float g_part[2][KSPLIT][BN * QN];   // ping-pong partial linear alphas (8 MB)
__device__ int   g_order[TN * BN];             // per-t batch indices sorted by symbol
__device__ int4  g_items[TN * 256];            // per-t work items: (symbol, start, cnt, pad)
__device__ int   g_nitems[TN];

// Packed dual-FMA (Blackwell f32x2)
__device__ __forceinline__ void fma2(unsigned long long& d,
                                     unsigned long long a,
                                     unsigned long long b) {
    asm("fma.rn.f32x2 %0, %1, %2, %0;" : "+l"(d) : "l"(a), "l"(b));
}
__device__ __forceinline__ unsigned long long pack2(float x) {
    unsigned long long r;
    unsigned u = __float_as_uint(x);
    asm("mov.b64 %0, {%1, %1};" : "=l"(r) : "r"(u));
    return r;
}

// ---------------------------------------------------------------------------
// P[s][q][q'] = exp(A[q][s][q'])
__global__ void exp_kernel(const float* __restrict__ A) {
    int i = blockIdx.x * 256 + threadIdx.x;       // 0 .. 128*256*256-1
    int j = i & 255;
    int q = (i >> 8) & 255;
    int s = i >> 16;
    g_P[(s << 16) + (q << 8) + j] = __expf(A[(q << 15) + (s << 8) + j]);
}

// ---------------------------------------------------------------------------
// Linear-space init: alpha0_lin[b][q] = init[q] (exp(log_init) == init, and
// init<=0 maps to exp(-1e30)=0). Partial 0 holds it; partials 1..3 zero.
__global__ void init_kernel(const float* __restrict__ init) {
    int b = blockIdx.x;
    int q = threadIdx.x;
    float iv = init[q];
    g_part[0][0][b * QN + q] = (iv > 0.0f) ? iv : 0.0f;
    #pragma unroll
    for (int j = 1; j < KSPLIT; j++) g_part[0][j][b * QN + q] = 0.0f;
}

// ---------------------------------------------------------------------------
// Per-timestep bucketing (unchanged): one CTA per t.
__global__ void bucket_kernel(const int* __restrict__ xs) {
    int t = blockIdx.x;
    int tid = threadIdx.x;
    __shared__ int cnt[SN];
    __shared__ int seg[SN];
    __shared__ int off[SN];
    if (tid < SN) cnt[tid] = 0;
    __syncthreads();
    for (int b = tid; b < BN; b += 256)
        atomicAdd(&cnt[xs[b * TN + t]], 1);
    __syncthreads();
    if (tid == 0) {
        int acc = 0;
        for (int s = 0; s < SN; s++) { seg[s] = acc; off[s] = acc; acc += cnt[s]; }
    }
    __syncthreads();
    for (int b = tid; b < BN; b += 256) {
        int s = xs[b * TN + t];
        int pos = atomicAdd(&off[s], 1);
        g_order[t * BN + pos] = b;
    }
    __syncthreads();
    if (tid == 0) {
        int ni = 0;
        for (int s = 0; s < SN; s++) {
            int c = cnt[s], st = seg[s];
            for (int o = 0; o < c; o += MTILE) {
                int m = c - o; if (m > MTILE) m = MTILE;
                g_items[t * 256 + ni] = make_int4(s, st + o, m, 0);
                ni++;
            }
        }
        g_nitems[t] = ni;
    }
}

// ---------------------------------------------------------------------------
// One FSA step, linear space, K-split. CTA (item, chunk kc) computes
//   part_out[kc][b][q'] = sum_{q in chunk} (alpha_lin[b][q]/256) * P[s][q][q']
// where alpha_lin = sum_j part_in[j][b][q]. Constant 1/256 renorm per step;
// the exact global scale 128*ln(256) is added back in final_kernel.
__global__ void __launch_bounds__(256) step_kernel(int t) {
    if (blockIdx.x >= g_nitems[t]) return;
    const float* __restrict__ pin  = &g_part[t & 1][0][0];
    float*       __restrict__ pout = &g_part[(t & 1) ^ 1][0][0];
    int4 it = g_items[t * 256 + blockIdx.x];
    const int s = it.x, start = it.y, cnt = it.z;
    const int kc = blockIdx.y;

    __shared__ __align__(16) float s_al[QCH][MTILE];  // [q][m] scaled linear alpha
    __shared__ int s_b[MTILE];

    const int tid = threadIdx.x;
    const int w = tid >> 5, lane = tid & 31;

    // Staging: warp w prepares batch element m=w's 64-q chunk (2 q per lane).
    if (w < cnt) {
        int b = g_order[t * BN + start + w];
        if (lane == 0) s_b[w] = b;
        const float* base = pin + b * QN + kc * QCH + 2 * lane;
        float2 a = make_float2(0.0f, 0.0f);
        #pragma unroll
        for (int j = 0; j < KSPLIT; j++) {
            float2 u = *(const float2*)(base + j * (BN * QN));
            a.x += u.x; a.y += u.y;
        }
        s_al[2 * lane][w]     = a.x * 0.00390625f;   // * 2^-8, exact
        s_al[2 * lane + 1][w] = a.y * 0.00390625f;
    } else {
        s_al[2 * lane][w] = 0.0f;
        s_al[2 * lane + 1][w] = 0.0f;
    }
    __syncthreads();

    unsigned long long acc[4] = {0ull, 0ull, 0ull, 0ull};  // m-pairs

    const float* __restrict__ Pp = g_P + (s << 16) + ((kc * QCH) << 8) + tid;
    #pragma unroll
    for (int q0 = 0; q0 < QCH; q0 += 8) {
        float p[8];
        #pragma unroll
        for (int i = 0; i < 8; i++)
            p[i] = __ldg(Pp + ((q0 + i) << 8));   // MLP=8, L2-resident, coalesced
        #pragma unroll
        for (int i = 0; i < 8; i++) {
            unsigned long long pp = pack2(p[i]);
            const ulonglong2* row = (const ulonglong2*)&s_al[q0 + i][0];
            ulonglong2 a0 = row[0];   // LDS.128 broadcast: m0..m3
            ulonglong2 a1 = row[1];   // LDS.128 broadcast: m4..m7
            fma2(acc[0], pp, a0.x);
            fma2(acc[1], pp, a0.y);
            fma2(acc[2], pp, a1.x);
            fma2(acc[3], pp, a1.y);
        }
    }

    float* __restrict__ po = pout + kc * (BN * QN) + tid;
    #pragma unroll
    for (int j = 0; j < 4; j++) {
        int m0 = 2 * j, m1 = 2 * j + 1;
        float lo = __uint_as_float((unsigned)(acc[j] & 0xFFFFFFFFull));
        float hi = __uint_as_float((unsigned)(acc[j] >> 32));
        if (m0 < cnt) po[s_b[m0] * QN] = lo;
        if (m1 < cnt) po[s_b[m1] * QN] = hi;
    }
}

// ---------------------------------------------------------------------------
// out[b] = log( sum_q alpha_lin[b][q] * exp(final[q]) ) + 128*ln(256)
// warp per batch element; alpha_lin = sum of KSPLIT partials (buffer 0, T even).
__global__ void final_kernel(const float* __restrict__ finalw, float* __restrict__ out) {
    int b = blockIdx.x * 8 + (threadIdx.x >> 5);
    int lane = threadIdx.x & 31;
    const float* ar = &g_part[0][0][0] + b * QN;
    float sum = 0.0f;
    #pragma unroll
    for (int i = 0; i < 8; i++) {
        int q = lane + 32 * i;
        float a = 0.0f;
        #pragma unroll
        for (int j = 0; j < KSPLIT; j++) a += ar[j * (BN * QN) + q];
        sum += a * __expf(finalw[q]);
    }
    #pragma unroll
    for (int o = 16; o > 0; o >>= 1) sum += __shfl_xor_sync(0xFFFFFFFFu, sum, o);
    if (lane == 0)
        out[b] = logf(sum) + (float)(128.0 * 5.545177444479562);  // T * ln(256)
}

// ---------------------------------------------------------------------------
extern "C" void kernel_launch(void* const* d_in, const int* in_sizes, int n_in,
                              void* d_out, int out_size) {
    const float* A      = (const float*)d_in[0];  // [Q,S,Q] fp32
    const float* init   = (const float*)d_in[1];  // [Q]
    const float* finalw = (const float*)d_in[2];  // [Q]
    const int*   xs     = (const int*)d_in[3];    // [B,T] int32
    float* out = (float*)d_out;                   // [B]

    exp_kernel<<<(SN * QN * QN) / 256, 256>>>(A);
    init_kernel<<<BN, QN>>>(init);
    bucket_kernel<<<TN, 256>>>(xs);
    for (int t = 0; t < TN; t++)
        step_kernel<<<dim3(256, KSPLIT), 256>>>(t);
    final_kernel<<<BN / 8, 256>>>(finalw, out);
}

// round 4
// speedup vs baseline: 3.0434x; 1.9211x over previous
#include <cuda_runtime.h>
#include <cuda_bf16.h>

// Problem constants
#define QN 256   // states
#define SN 128   // symbols
#define BN 1024  // batch
#define TN 128   // timesteps
#define MT 16    // batch elements per work item (MMA M = 16)
#define KSP 2    // q-chunks per item (K split)
#define KCH 128  // K per CTA chunk
#define GRIDX 192  // max items per step: sum ceil(c/16) <= 128 + 1024/16 = 192

// Device scratch (allocation-free rule: static __device__ globals)
__device__ unsigned g_Pbf[SN * QN * QN / 2];   // bf16x2 exp(A), [s][q][q'] : 16 MB
__device__ float g_part[2][KSP][BN * QN];      // ping-pong partial linear alphas
__device__ int   g_order[TN * BN];
__device__ int4  g_items[TN * GRIDX];
__device__ int   g_nitems[TN];

// SMEM layout (bytes)
#define A_OFF   0
#define A_ROW   272                     // 16 rows x (128 bf16 + 8 pad) -> conflict-free ldmatrix
#define P_OFF   4352
#define P_ROW   528                     // 32 rows x (256 bf16 + 8 pad)
#define P_SLAB  16896
#define SB_OFF  (P_OFF + 2 * P_SLAB)    // 38144
#define SH_BYTES (SB_OFF + 64)

// ---------------------------------------------------------------------------
__device__ __forceinline__ unsigned f22bf(float lo, float hi) {
    unsigned r;
    asm("cvt.rn.bf16x2.f32 %0, %1, %2;" : "=r"(r) : "f"(hi), "f"(lo));  // a->hi, b->lo
    return r;
}
__device__ __forceinline__ void ldmA(unsigned a[4], unsigned addr) {
    asm volatile("ldmatrix.sync.aligned.m8n8.x4.shared.b16 {%0,%1,%2,%3}, [%4];"
                 : "=r"(a[0]), "=r"(a[1]), "=r"(a[2]), "=r"(a[3]) : "r"(addr));
}
__device__ __forceinline__ void ldmBT(unsigned b[4], unsigned addr) {
    asm volatile("ldmatrix.sync.aligned.m8n8.x4.trans.shared.b16 {%0,%1,%2,%3}, [%4];"
                 : "=r"(b[0]), "=r"(b[1]), "=r"(b[2]), "=r"(b[3]) : "r"(addr));
}
__device__ __forceinline__ void mma16816(float d[4], const unsigned a[4],
                                         unsigned b0, unsigned b1) {
    asm volatile("mma.sync.aligned.m16n8k16.row.col.f32.bf16.bf16.f32 "
                 "{%0,%1,%2,%3},{%4,%5,%6,%7},{%8,%9},{%0,%1,%2,%3};"
                 : "+f"(d[0]), "+f"(d[1]), "+f"(d[2]), "+f"(d[3])
                 : "r"(a[0]), "r"(a[1]), "r"(a[2]), "r"(a[3]), "r"(b0), "r"(b1));
}
__device__ __forceinline__ void cpasync16(unsigned saddr, const void* g) {
    asm volatile("cp.async.cg.shared.global [%0], [%1], 16;" :: "r"(saddr), "l"(g));
}

// ---------------------------------------------------------------------------
// P_bf16[s][q][q'] = bf16(exp(A[q][s][q'])), packed as bf16x2 (q' pairs)
__global__ void exp_kernel(const float* __restrict__ A) {
    int i = blockIdx.x * 256 + threadIdx.x;   // one thread per q'-pair
    int j2 = i & 127;
    int q = (i >> 7) & 255;
    int s = i >> 15;
    float2 v = *(const float2*)(A + (q << 15) + (s << 8) + 2 * j2);
    g_Pbf[(s << 15) + (q << 7) + j2] = f22bf(__expf(v.x), __expf(v.y));
}

// ---------------------------------------------------------------------------
__global__ void init_kernel(const float* __restrict__ init) {
    int b = blockIdx.x;
    int q = threadIdx.x;
    float iv = init[q];
    g_part[0][0][b * QN + q] = (iv > 0.0f) ? iv : 0.0f;
    g_part[0][1][b * QN + q] = 0.0f;
}

// ---------------------------------------------------------------------------
// Per-timestep bucketing: items of <= MT elements sharing a symbol.
__global__ void bucket_kernel(const int* __restrict__ xs) {
    int t = blockIdx.x;
    int tid = threadIdx.x;
    __shared__ int cnt[SN];
    __shared__ int seg[SN];
    __shared__ int off[SN];
    if (tid < SN) cnt[tid] = 0;
    __syncthreads();
    for (int b = tid; b < BN; b += 256)
        atomicAdd(&cnt[xs[b * TN + t]], 1);
    __syncthreads();
    if (tid == 0) {
        int acc = 0;
        for (int s = 0; s < SN; s++) { seg[s] = acc; off[s] = acc; acc += cnt[s]; }
    }
    __syncthreads();
    for (int b = tid; b < BN; b += 256) {
        int s = xs[b * TN + t];
        int pos = atomicAdd(&off[s], 1);
        g_order[t * BN + pos] = b;
    }
    __syncthreads();
    if (tid == 0) {
        int ni = 0;
        for (int s = 0; s < SN; s++) {
            int c = cnt[s], st = seg[s];
            for (int o = 0; o < c; o += MT) {
                int m = c - o; if (m > MT) m = MT;
                g_items[t * GRIDX + ni] = make_int4(s, st + o, m, 0);
                ni++;
            }
        }
        g_nitems[t] = ni;
    }
}

// ---------------------------------------------------------------------------
// One FSA step via bf16 tensor-core GEMM per (item, k-chunk):
//   D[m=16 batch, n=256 q'] = alpha_bf16[m, k in chunk] x P_bf16[s][k, q']
// alpha staged with the exact 2^-8 renorm; compensation added in final_kernel.
__global__ void __launch_bounds__(256) step_kernel(int t) {
    if (blockIdx.x >= g_nitems[t]) return;
    __shared__ __align__(16) unsigned char sh[SH_BYTES];
    unsigned shb = (unsigned)__cvta_generic_to_shared(sh);
    const int4 it = g_items[t * GRIDX + blockIdx.x];
    const int s = it.x, start = it.y, cnt = it.z;
    const int kc = blockIdx.y;                       // 0..KSP-1
    const float* __restrict__ pin = &g_part[t & 1][0][0];
    float* __restrict__ pout = &g_part[(t & 1) ^ 1][kc][0];
    const int tid = threadIdx.x;
    const int w = tid >> 5, lane = tid & 31;

    // ---- stage A: alpha (sum of partials, * 2^-8) -> bf16 SMEM [16][128+pad]
    {
        int row = tid >> 4;     // batch slot 0..15
        int seg = tid & 15;     // 8 k-values each
        uint4 pk;
        if (row < cnt) {
            int b = g_order[t * BN + start + row];
            const float* p0 = pin + b * QN + kc * KCH + seg * 8;
            const float* p1 = p0 + BN * QN;
            float4 x0 = *(const float4*)p0, x1 = *(const float4*)(p0 + 4);
            float4 y0 = *(const float4*)p1, y1 = *(const float4*)(p1 + 4);
            const float sc = 0.00390625f;   // 2^-8 exact
            pk.x = f22bf((x0.x + y0.x) * sc, (x0.y + y0.y) * sc);
            pk.y = f22bf((x0.z + y0.z) * sc, (x0.w + y0.w) * sc);
            pk.z = f22bf((x1.x + y1.x) * sc, (x1.y + y1.y) * sc);
            pk.w = f22bf((x1.z + y1.z) * sc, (x1.w + y1.w) * sc);
        } else {
            pk = make_uint4(0, 0, 0, 0);
        }
        *(uint4*)(sh + A_OFF + row * A_ROW + seg * 16) = pk;
        if (tid < MT)
            ((int*)(sh + SB_OFF))[tid] = (tid < cnt) ? g_order[t * BN + start + tid] : 0;
    }

    // ---- cp.async fill of P k-slab (32 rows x 512B, contiguous in global)
    const char* gP = (const char*)g_Pbf + ((size_t)s << 17) + (size_t)kc * KCH * 512;
    auto fill = [&](int ks) {
        const char* gsrc = gP + (size_t)ks * 32 * 512;
        unsigned sdst = shb + P_OFF + (ks & 1) * P_SLAB;
        #pragma unroll
        for (int i = 0; i < 4; i++) {
            int c = tid + 256 * i;
            int r = c >> 5, col = c & 31;
            cpasync16(sdst + r * P_ROW + col * 16, gsrc + r * 512 + col * 16);
        }
        asm volatile("cp.async.commit_group;");
    };

    fill(0);
    __syncthreads();   // A-stage visible to all warps

    float d[4][4];
    #pragma unroll
    for (int j = 0; j < 4; j++)
        #pragma unroll
        for (int r = 0; r < 4; r++) d[j][r] = 0.0f;

    #pragma unroll
    for (int ks = 0; ks < 4; ks++) {
        if (ks < 3) {
            fill(ks + 1);
            asm volatile("cp.async.wait_group 1;");
        } else {
            asm volatile("cp.async.wait_group 0;");
        }
        __syncthreads();
        unsigned pbase = shb + P_OFF + (ks & 1) * P_SLAB;
        #pragma unroll
        for (int k16 = 0; k16 < 2; k16++) {
            unsigned a[4];
            ldmA(a, shb + A_OFF + (lane & 15) * A_ROW
                     + (ks * 32 + k16 * 16 + (lane >> 4) * 8) * 2);
            unsigned b[8];
            unsigned baddr = pbase + (k16 * 16 + (lane & 15)) * P_ROW
                             + (w * 32 + (lane >> 4) * 8) * 2;
            ldmBT(b + 0, baddr);        // n-tiles 0,1 (q' w*32 .. +16)
            ldmBT(b + 4, baddr + 32);   // n-tiles 2,3 (q' +16 .. +32)
            mma16816(d[0], a, b[0], b[1]);
            mma16816(d[1], a, b[2], b[3]);
            mma16816(d[2], a, b[4], b[5]);
            mma16816(d[3], a, b[6], b[7]);
        }
        __syncthreads();   // protect slab buffer before next refill
    }

    // ---- epilogue: D frag (m=l/4(+8), n=2(l%4)+{0,1}) -> pout[b][q']
    const int* sb = (const int*)(sh + SB_OFF);
    int m0 = lane >> 2;
    int q0 = w * 32 + 2 * (lane & 3);
    #pragma unroll
    for (int j = 0; j < 4; j++) {
        int n = q0 + j * 8;
        if (m0 < cnt)
            *(float2*)(pout + sb[m0] * QN + n) = make_float2(d[j][0], d[j][1]);
        if (m0 + 8 < cnt)
            *(float2*)(pout + sb[m0 + 8] * QN + n) = make_float2(d[j][2], d[j][3]);
    }
}

// ---------------------------------------------------------------------------
// out[b] = log( sum_q alpha_lin[b][q] * exp(final[q]) ) + 128*ln(256)
__global__ void final_kernel(const float* __restrict__ finalw, float* __restrict__ out) {
    int b = blockIdx.x * 8 + (threadIdx.x >> 5);
    int lane = threadIdx.x & 31;
    const float* ar = &g_part[0][0][0] + b * QN;   // T=128 even -> buffer 0
    float sum = 0.0f;
    #pragma unroll
    for (int i = 0; i < 8; i++) {
        int q = lane + 32 * i;
        float a = ar[q] + ar[BN * QN + q];
        sum += a * __expf(finalw[q]);
    }
    #pragma unroll
    for (int o = 16; o > 0; o >>= 1) sum += __shfl_xor_sync(0xFFFFFFFFu, sum, o);
    if (lane == 0)
        out[b] = logf(sum) + (float)(128.0 * 5.545177444479562);  // T * ln(256)
}

// ---------------------------------------------------------------------------
extern "C" void kernel_launch(void* const* d_in, const int* in_sizes, int n_in,
                              void* d_out, int out_size) {
    const float* A      = (const float*)d_in[0];  // [Q,S,Q] fp32
    const float* init   = (const float*)d_in[1];  // [Q]
    const float* finalw = (const float*)d_in[2];  // [Q]
    const int*   xs     = (const int*)d_in[3];    // [B,T] int32
    float* out = (float*)d_out;                   // [B]

    exp_kernel<<<(SN * QN * QN / 2) / 256, 256>>>(A);
    init_kernel<<<BN, QN>>>(init);
    bucket_kernel<<<TN, 256>>>(xs);
    for (int t = 0; t < TN; t++)
        step_kernel<<<dim3(GRIDX, KSP), 256>>>(t);
    final_kernel<<<BN / 8, 256>>>(finalw, out);
}